// round 9
// baseline (speedup 1.0000x reference)
#include <cuda_runtime.h>

#define NS 8192
#define NH 64
#define CC 64
#define TILES 4
#define ROWCAP 160   // binomial(8192,0.01): mean 82, std 9 -> 8.7 sigma margin

// Scratch (allocation-free rule: __device__ globals)
__device__ float g_X1[NS * CC];
__device__ float g_X2[NS * CC];
__device__ int   g_cnt[NS];
__device__ int   g_idx[NS * ROWCAP];
__device__ float g_v [NS * ROWCAP];
__device__ float g_b [NS * ROWCAP];

// ---------------------------------------------------------------------------
// Kernel 1: 4 tiles (s values) per CTA, 256 threads, all 16 float4 loads
// front-batched. Register-resident reductions. Also zeroes g_cnt (blocks 0-31).
// ---------------------------------------------------------------------------
__global__ void __launch_bounds__(256) prep_kernel(
    const float* __restrict__ Hp, const float* __restrict__ w1,
    const float* __restrict__ W2, const float* __restrict__ w3)
{
    __shared__ float t_sm[TILES][64];
    const int s0   = blockIdx.x * TILES;
    const int tid  = threadIdx.x;
    const int lane = tid & 31;

    if (blockIdx.x < 32) g_cnt[blockIdx.x * 256 + tid] = 0;

    ((float*)t_sm)[tid] = 0.f;   // 256 floats == TILES*64

    // Front-batched streaming loads (read-once: evict-first)
    const float4* base = (const float4*)(Hp + (size_t)s0 * (CC * NH));
    float4 v[TILES][4];
    #pragma unroll
    for (int p = 0; p < TILES; p++)
        #pragma unroll
        for (int k = 0; k < 4; k++)
            v[p][k] = __ldcs(base + p * 1024 + tid + 256 * k);

    const int h0 = (tid & 15) * 4;
    const int c0 = tid >> 4;
    const float w3v0 = __ldg(w3 + h0),     w3v1 = __ldg(w3 + h0 + 1);
    const float w3v2 = __ldg(w3 + h0 + 2), w3v3 = __ldg(w3 + h0 + 3);
    float w1c[4];
    #pragma unroll
    for (int k = 0; k < 4; k++) w1c[k] = __ldg(w1 + c0 + 16 * k);

    __syncthreads();   // t_sm init visible before atomics

    #pragma unroll
    for (int p = 0; p < TILES; p++) {
        float tq0 = 0.f, tq1 = 0.f, tq2 = 0.f, tq3 = 0.f;
        #pragma unroll
        for (int k = 0; k < 4; k++) {
            tq0 += v[p][k].x * w1c[k];  tq1 += v[p][k].y * w1c[k];
            tq2 += v[p][k].z * w1c[k];  tq3 += v[p][k].w * w1c[k];

            float d = v[p][k].x * w3v0 + v[p][k].y * w3v1
                    + v[p][k].z * w3v2 + v[p][k].w * w3v3;
            #pragma unroll
            for (int o = 8; o; o >>= 1) d += __shfl_xor_sync(0xffffffffu, d, o);
            if ((lane & 15) == 0)
                g_X2[(size_t)(s0 + p) * CC + c0 + 16 * k] = d;
        }
        tq0 += __shfl_xor_sync(0xffffffffu, tq0, 16);
        tq1 += __shfl_xor_sync(0xffffffffu, tq1, 16);
        tq2 += __shfl_xor_sync(0xffffffffu, tq2, 16);
        tq3 += __shfl_xor_sync(0xffffffffu, tq3, 16);
        if (lane < 16) {
            atomicAdd(&t_sm[p][h0],     tq0);
            atomicAdd(&t_sm[p][h0 + 1], tq1);
            atomicAdd(&t_sm[p][h0 + 2], tq2);
            atomicAdd(&t_sm[p][h0 + 3], tq3);
        }
    }
    __syncthreads();

    // X1[c'] = sum_h t[h] * W2[c'][h] : 4 lanes per c', all tiles
    const int cp   = tid >> 2;
    const int part = tid & 3;
    const float4* w2v = (const float4*)(W2 + cp * NH + part * 16);
    float4 w[4];
    #pragma unroll
    for (int j = 0; j < 4; j++) w[j] = __ldg(&w2v[j]);

    #pragma unroll
    for (int p = 0; p < TILES; p++) {
        const float* tp = &t_sm[p][part * 16];
        float acc = 0.f;
        #pragma unroll
        for (int j = 0; j < 4; j++)
            acc += w[j].x * tp[4*j] + w[j].y * tp[4*j+1]
                 + w[j].z * tp[4*j+2] + w[j].w * tp[4*j+3];
        acc += __shfl_xor_sync(0xffffffffu, acc, 1);
        acc += __shfl_xor_sync(0xffffffffu, acc, 2);
        if (part == 0) g_X1[(size_t)(s0 + p) * CC + cp] = acc;
    }
}

// ---------------------------------------------------------------------------
// Kernel 2: barrier-free streamer. Read mask uint4 + write zero float4 at the
// same index (pure coalesced stream); compact hits into per-row lists with
// fused V/B gather. Spread atomics (8192 counters, ~82 ops each).
// ---------------------------------------------------------------------------
__global__ void __launch_bounds__(512) scan_kernel(
    const float* __restrict__ V, const float* __restrict__ B,
    const unsigned int* __restrict__ mask, float* __restrict__ out)
{
    const int gid = blockIdx.x * 512 + threadIdx.x;   // 4096 * 512 threads
    const uint4* mv = (const uint4*)mask;
    float4* out4 = (float4*)out;
    const float4 z4 = make_float4(0.f, 0.f, 0.f, 0.f);

    #pragma unroll
    for (int k = 0; k < 8; k++) {
        const int i = gid + k * (4096 * 512);   // < 16,777,216
        uint4 u = __ldcs(mv + i);
        __stcs(out4 + i, z4);
        if (u.x | u.y | u.z | u.w) {
            const int e0    = i * 4;            // 4 elems share one row
            const int row   = e0 >> 13;
            const int rbase = row * ROWCAP;
            #pragma unroll
            for (int q = 0; q < 4; q++) {
                const unsigned int bit = (q == 0) ? u.x : (q == 1) ? u.y
                                       : (q == 2) ? u.z : u.w;
                if (bit) {
                    const int p = atomicAdd(&g_cnt[row], 1);
                    if (p < ROWCAP) {
                        g_idx[rbase + p] = e0 + q;
                        g_v [rbase + p] = __ldcs(V + e0 + q);
                        g_b [rbase + p] = __ldcs(B + e0 + q);
                    }
                }
            }
        }
    }
}

// ---------------------------------------------------------------------------
// Kernel 3: one 128-thr CTA per row. Compact inputs only; X1/X2 from L2.
// Half-warp per element, smem rowsum, scatter e*inv over the zeros.
// ---------------------------------------------------------------------------
__global__ void __launch_bounds__(128) solve_kernel(float* __restrict__ out)
{
    __shared__ __align__(16) float x1s[64];
    __shared__ float e_c[ROWCAP];
    __shared__ float rowsum;

    const int s    = blockIdx.x;
    const int tid  = threadIdx.x;
    const int lane = tid & 31;
    const int wid  = tid >> 5;                 // 0..3
    const int rb   = s * ROWCAP;

    if (tid == 0) rowsum = 1e-6f;
    if (tid < 64) x1s[tid] = g_X1[(size_t)s * CC + tid];
    int m = g_cnt[s]; if (m > ROWCAP) m = ROWCAP;
    __syncthreads();

    const int half = lane >> 4;                // 0 or 1
    const int hl   = lane & 15;
    const unsigned hmask = 0xFFFFu << (half * 16);
    const float4 x1v = *(const float4*)(x1s + hl * 4);
    float lsum = 0.f;

    for (int el = wid * 2 + half; el < m; el += 8) {   // 8 half-warps
        const int j  = g_idx[rb + el] & (NS - 1);
        const float bb = __ldg(g_b + rb + el);         // broadcast
        const float vv = __ldg(g_v + rb + el);
        const float4 xv = __ldg((const float4*)(g_X2 + (size_t)j * CC) + hl);
        float p = xv.x * x1v.x + xv.y * x1v.y + xv.z * x1v.z + xv.w * x1v.w;
        #pragma unroll
        for (int o = 8; o; o >>= 1) p += __shfl_xor_sync(hmask, p, o);
        if (hl == 0) {
            const float sg = 1.f / (1.f + expf(-(p + bb)));
            const float ev = expf(vv * sg);
            e_c[el] = ev;
            lsum += ev;
        }
    }

    #pragma unroll
    for (int o = 16; o; o >>= 1) lsum += __shfl_down_sync(0xffffffffu, lsum, o);
    if (lane == 0 && lsum != 0.f) atomicAdd(&rowsum, lsum);
    __syncthreads();

    const float inv = 1.f / rowsum;
    for (int el = tid; el < m; el += 128)
        __stcs(out + g_idx[rb + el], e_c[el] * inv);
}

extern "C" void kernel_launch(void* const* d_in, const int* in_sizes, int n_in,
                              void* d_out, int out_size)
{
    (void)in_sizes; (void)n_in; (void)out_size;
    const float* Hp  = (const float*)d_in[0];
    const float* w1  = (const float*)d_in[1];
    const float* W2  = (const float*)d_in[2];
    const float* w3  = (const float*)d_in[3];
    const float* V   = (const float*)d_in[4];
    const float* B   = (const float*)d_in[5];
    const unsigned int* mask = (const unsigned int*)d_in[6];
    float* out = (float*)d_out;

    prep_kernel<<<NS / TILES, 256>>>(Hp, w1, W2, w3);
    scan_kernel<<<4096, 512>>>(V, B, mask, out);
    solve_kernel<<<NS, 128>>>(out);
}

// round 10
// speedup vs baseline: 1.0265x; 1.0265x over previous
#include <cuda_runtime.h>

#define NS 8192
#define NH 64
#define CC 64
#define TILES 4

// Scratch (allocation-free rule: __device__ globals)
__device__ float g_X1[NS * CC];
__device__ float g_X2[NS * CC];

// ---------------------------------------------------------------------------
// Kernel 1 (unchanged from R8): 4 tiles per CTA, 256 threads, all 16 float4
// loads front-batched. Register-resident reductions.
// ---------------------------------------------------------------------------
__global__ void __launch_bounds__(256) prep_kernel(
    const float* __restrict__ Hp, const float* __restrict__ w1,
    const float* __restrict__ W2, const float* __restrict__ w3)
{
    __shared__ float t_sm[TILES][64];
    const int s0   = blockIdx.x * TILES;
    const int tid  = threadIdx.x;
    const int lane = tid & 31;

    ((float*)t_sm)[tid] = 0.f;   // 256 floats == TILES*64

    // Front-batched streaming loads (read-once: evict-first)
    const float4* base = (const float4*)(Hp + (size_t)s0 * (CC * NH));
    float4 v[TILES][4];
    #pragma unroll
    for (int p = 0; p < TILES; p++)
        #pragma unroll
        for (int k = 0; k < 4; k++)
            v[p][k] = __ldcs(base + p * 1024 + tid + 256 * k);

    const int h0 = (tid & 15) * 4;
    const int c0 = tid >> 4;
    const float w3v0 = __ldg(w3 + h0),     w3v1 = __ldg(w3 + h0 + 1);
    const float w3v2 = __ldg(w3 + h0 + 2), w3v3 = __ldg(w3 + h0 + 3);
    float w1c[4];
    #pragma unroll
    for (int k = 0; k < 4; k++) w1c[k] = __ldg(w1 + c0 + 16 * k);

    __syncthreads();   // t_sm init visible before atomics

    #pragma unroll
    for (int p = 0; p < TILES; p++) {
        float tq0 = 0.f, tq1 = 0.f, tq2 = 0.f, tq3 = 0.f;
        #pragma unroll
        for (int k = 0; k < 4; k++) {
            tq0 += v[p][k].x * w1c[k];  tq1 += v[p][k].y * w1c[k];
            tq2 += v[p][k].z * w1c[k];  tq3 += v[p][k].w * w1c[k];

            float d = v[p][k].x * w3v0 + v[p][k].y * w3v1
                    + v[p][k].z * w3v2 + v[p][k].w * w3v3;
            #pragma unroll
            for (int o = 8; o; o >>= 1) d += __shfl_xor_sync(0xffffffffu, d, o);
            if ((lane & 15) == 0)
                g_X2[(size_t)(s0 + p) * CC + c0 + 16 * k] = d;
        }
        tq0 += __shfl_xor_sync(0xffffffffu, tq0, 16);
        tq1 += __shfl_xor_sync(0xffffffffu, tq1, 16);
        tq2 += __shfl_xor_sync(0xffffffffu, tq2, 16);
        tq3 += __shfl_xor_sync(0xffffffffu, tq3, 16);
        if (lane < 16) {
            atomicAdd(&t_sm[p][h0],     tq0);
            atomicAdd(&t_sm[p][h0 + 1], tq1);
            atomicAdd(&t_sm[p][h0 + 2], tq2);
            atomicAdd(&t_sm[p][h0 + 3], tq3);
        }
    }
    __syncthreads();

    const int cp   = tid >> 2;
    const int part = tid & 3;
    const float4* w2v = (const float4*)(W2 + cp * NH + part * 16);
    float4 w[4];
    #pragma unroll
    for (int j = 0; j < 4; j++) w[j] = __ldg(&w2v[j]);

    #pragma unroll
    for (int p = 0; p < TILES; p++) {
        const float* tp = &t_sm[p][part * 16];
        float acc = 0.f;
        #pragma unroll
        for (int j = 0; j < 4; j++)
            acc += w[j].x * tp[4*j] + w[j].y * tp[4*j+1]
                 + w[j].z * tp[4*j+2] + w[j].w * tp[4*j+3];
        acc += __shfl_xor_sync(0xffffffffu, acc, 1);
        acc += __shfl_xor_sync(0xffffffffu, acc, 2);
        if (part == 0) g_X1[(size_t)(s0 + p) * CC + cp] = acc;
    }
}

// ---------------------------------------------------------------------------
// Kernel 2: one CTA (512 thr) per row s. Warp-local immediate gather:
//  - front-batch mask loads (evict-first), zero-write the row early (streaming)
//  - each warp ballots its own scanned elements; on discovery the WHOLE warp
//    immediately does the X2[j]·X1 dot (2 floats/lane, 5-shfl reduce), lane0
//    finishes sigmoid/exp and appends (j, e) via one smem atomic.
//  - NO barrier between scan and gather; one barrier before the scaled scatter.
// ---------------------------------------------------------------------------
#define MAXM 1024   // binomial(8192, 0.01): mean 82, std 9 — >100 sigma margin

__global__ void __launch_bounds__(512) row_kernel(
    const float* __restrict__ V, const float* __restrict__ B,
    const unsigned int* __restrict__ mask, float* __restrict__ out)
{
    __shared__ int   idxs[MAXM];    // 4 KB appended column indices
    __shared__ float e_c[MAXM];     // 4 KB appended e values
    __shared__ float x1s[64];
    __shared__ float rowsum;
    __shared__ int   cnt;

    const int s    = blockIdx.x;
    const int tid  = threadIdx.x;
    const int lane = tid & 31;
    const size_t rowoff = (size_t)s * NS;

    if (tid == 0) { cnt = 0; rowsum = 1e-6f; }
    if (tid < 64) x1s[tid] = g_X1[(size_t)s * CC + tid];

    // Front-batch the mask loads (evict-first: read exactly once)
    const uint4* mv = (const uint4*)(mask + rowoff);
    uint4 u[4];
    #pragma unroll
    for (int k = 0; k < 4; k++) u[k] = __ldcs(mv + tid + k * 512);

    // Fire-and-forget streaming zero write of the output row
    float4* out4 = (float4*)(out + rowoff);
    const float4 z4 = make_float4(0.f, 0.f, 0.f, 0.f);
    #pragma unroll
    for (int k = 0; k < 4; k++) __stcs(out4 + tid + k * 512, z4);

    __syncthreads();   // cnt/rowsum/x1s visible

    // --- Scan + immediate warp-cooperative gather (no intermediate barrier) --
    const float x1a = x1s[lane];
    const float x1b = x1s[lane + 32];
    float lsum = 0.f;   // accumulated on lane 0 only

    #pragma unroll
    for (int k = 0; k < 4; k++) {
        const int bj = (tid + k * 512) * 4;
        #pragma unroll
        for (int q = 0; q < 4; q++) {
            const unsigned int bit = (q == 0) ? u[k].x : (q == 1) ? u[k].y
                                   : (q == 2) ? u[k].z : u[k].w;
            unsigned int bal = __ballot_sync(0xffffffffu, bit != 0u);
            while (bal) {
                const int src = __ffs(bal) - 1;
                bal &= bal - 1;
                const int j = __shfl_sync(0xffffffffu, bj + q, src);
                const float bb = __ldg(B + rowoff + j);   // warp broadcast
                const float vv = __ldg(V + rowoff + j);
                const float* x2 = g_X2 + (size_t)j * CC;  // L2-resident
                float p = __ldg(x2 + lane) * x1a + __ldg(x2 + lane + 32) * x1b;
                #pragma unroll
                for (int o = 16; o; o >>= 1)
                    p += __shfl_xor_sync(0xffffffffu, p, o);
                if (lane == 0) {
                    const float sg = 1.f / (1.f + expf(-(p + bb)));
                    const float ev = expf(vv * sg);
                    const int pos = atomicAdd(&cnt, 1);
                    idxs[pos] = j;
                    e_c[pos]  = ev;
                    lsum += ev;
                }
            }
        }
    }

    // --- Row sum: one smem atomic per warp ----------------------------------
    if (lane == 0 && lsum != 0.f) atomicAdd(&rowsum, lsum);
    __syncthreads();
    const int m = cnt;

    // --- Sparse scatter of scaled values over the zeros ---------------------
    const float inv = 1.f / rowsum;
    for (int el = tid; el < m; el += 512)
        __stcs(out + rowoff + idxs[el], e_c[el] * inv);
}

extern "C" void kernel_launch(void* const* d_in, const int* in_sizes, int n_in,
                              void* d_out, int out_size)
{
    (void)in_sizes; (void)n_in; (void)out_size;
    const float* Hp  = (const float*)d_in[0];
    const float* w1  = (const float*)d_in[1];
    const float* W2  = (const float*)d_in[2];
    const float* w3  = (const float*)d_in[3];
    const float* V   = (const float*)d_in[4];
    const float* B   = (const float*)d_in[5];
    const unsigned int* mask = (const unsigned int*)d_in[6];
    float* out = (float*)d_out;

    prep_kernel<<<NS / TILES, 256>>>(Hp, w1, W2, w3);
    row_kernel<<<NS, 512>>>(V, B, mask, out);
}

// round 11
// speedup vs baseline: 1.4425x; 1.4052x over previous
#include <cuda_runtime.h>

#define NS 8192
#define NH 64
#define CC 64

// Scratch (allocation-free rule: __device__ globals)
__device__ float g_X1[NS * CC];
__device__ float g_X2[NS * CC];

// ---------------------------------------------------------------------------
// Kernel 1: 2 tiles per CTA, 512 threads (high occupancy), 4 float4 loads per
// thread front-batched. i = tid + 512k -> fixed h-quad h0=(tid&15)*4,
// c = tid>>4 + 32k (2048 % 64 == 0 keeps h fixed across k).
// ---------------------------------------------------------------------------
__global__ void __launch_bounds__(512) prep_kernel(
    const float* __restrict__ Hp, const float* __restrict__ w1,
    const float* __restrict__ W2, const float* __restrict__ w3)
{
    __shared__ float t_sm[2][64];
    const int s0   = blockIdx.x * 2;
    const int tid  = threadIdx.x;
    const int lane = tid & 31;

    if (tid < 128) ((float*)t_sm)[tid] = 0.f;

    // Front-batched streaming loads (read-once: evict-first)
    const float4* base = (const float4*)(Hp + (size_t)s0 * (CC * NH));
    float4 v[2][2];
    #pragma unroll
    for (int p = 0; p < 2; p++)
        #pragma unroll
        for (int k = 0; k < 2; k++)
            v[p][k] = __ldcs(base + p * 1024 + tid + 512 * k);

    const int h0 = (tid & 15) * 4;
    const int c0 = tid >> 4;                    // 0..31
    const float w3v0 = __ldg(w3 + h0),     w3v1 = __ldg(w3 + h0 + 1);
    const float w3v2 = __ldg(w3 + h0 + 2), w3v3 = __ldg(w3 + h0 + 3);
    float w1c[2];
    #pragma unroll
    for (int k = 0; k < 2; k++) w1c[k] = __ldg(w1 + c0 + 32 * k);

    __syncthreads();   // t_sm init visible before atomics

    #pragma unroll
    for (int p = 0; p < 2; p++) {
        float tq0 = 0.f, tq1 = 0.f, tq2 = 0.f, tq3 = 0.f;
        #pragma unroll
        for (int k = 0; k < 2; k++) {
            tq0 += v[p][k].x * w1c[k];  tq1 += v[p][k].y * w1c[k];
            tq2 += v[p][k].z * w1c[k];  tq3 += v[p][k].w * w1c[k];

            // X2[c]: dot4 with w3, reduce across the 16-lane half sharing c
            float d = v[p][k].x * w3v0 + v[p][k].y * w3v1
                    + v[p][k].z * w3v2 + v[p][k].w * w3v3;
            #pragma unroll
            for (int o = 8; o; o >>= 1) d += __shfl_xor_sync(0xffffffffu, d, o);
            if ((lane & 15) == 0)
                g_X2[(size_t)(s0 + p) * CC + c0 + 32 * k] = d;
        }
        // t[h0..h0+3]: pair-combine lanes l / l+16, spread smem atomics
        tq0 += __shfl_xor_sync(0xffffffffu, tq0, 16);
        tq1 += __shfl_xor_sync(0xffffffffu, tq1, 16);
        tq2 += __shfl_xor_sync(0xffffffffu, tq2, 16);
        tq3 += __shfl_xor_sync(0xffffffffu, tq3, 16);
        if (lane < 16) {
            atomicAdd(&t_sm[p][h0],     tq0);
            atomicAdd(&t_sm[p][h0 + 1], tq1);
            atomicAdd(&t_sm[p][h0 + 2], tq2);
            atomicAdd(&t_sm[p][h0 + 3], tq3);
        }
    }
    __syncthreads();

    // X1[c'] = sum_h t[h] * W2[c'][h] : 8 lanes per c' (512 thr / 64 outputs)
    const int cp   = tid >> 3;                  // 0..63
    const int part = tid & 7;                   // 0..7, 8 h each
    const float4* w2v = (const float4*)(W2 + cp * NH + part * 8);
    float4 wa = __ldg(&w2v[0]);
    float4 wb = __ldg(&w2v[1]);

    #pragma unroll
    for (int p = 0; p < 2; p++) {
        const float* tp = &t_sm[p][part * 8];
        float acc = wa.x * tp[0] + wa.y * tp[1] + wa.z * tp[2] + wa.w * tp[3]
                  + wb.x * tp[4] + wb.y * tp[5] + wb.z * tp[6] + wb.w * tp[7];
        acc += __shfl_xor_sync(0xffffffffu, acc, 1);
        acc += __shfl_xor_sync(0xffffffffu, acc, 2);
        acc += __shfl_xor_sync(0xffffffffu, acc, 4);
        if (part == 0) g_X1[(size_t)(s0 + p) * CC + cp] = acc;
    }
}

// ---------------------------------------------------------------------------
// Kernel 2: one CTA (512 thr) per row s — exact R8 version (128.0 us, 96% occ).
// ---------------------------------------------------------------------------
#define MAXM 2048   // binomial(8192, 0.01): mean 82, std 9 — huge margin

__global__ void __launch_bounds__(512) row_kernel(
    const float* __restrict__ V, const float* __restrict__ B,
    const unsigned int* __restrict__ mask, float* __restrict__ out)
{
    __shared__ int   idxs[MAXM];    // 8 KB compacted column indices
    __shared__ float e_c[MAXM];     // 8 KB compacted e values
    __shared__ float x1s[64];
    __shared__ float rowsum;
    __shared__ int   cnt;

    const int s    = blockIdx.x;
    const int tid  = threadIdx.x;
    const int lane = tid & 31;
    const int wid  = tid >> 5;
    const size_t rowoff = (size_t)s * NS;

    if (tid == 0) { cnt = 0; rowsum = 1e-6f; }
    if (tid < 64) x1s[tid] = g_X1[(size_t)s * CC + tid];

    // Front-batch the mask loads (evict-first: read exactly once)
    const uint4* mv = (const uint4*)(mask + rowoff);
    uint4 u[4];
    #pragma unroll
    for (int k = 0; k < 4; k++) u[k] = __ldcs(mv + tid + k * 512);

    // Fire-and-forget streaming zero write of the output row
    float4* out4 = (float4*)(out + rowoff);
    const float4 z4 = make_float4(0.f, 0.f, 0.f, 0.f);
    #pragma unroll
    for (int k = 0; k < 4; k++) __stcs(out4 + tid + k * 512, z4);

    __syncthreads();   // cnt/rowsum/x1s visible

    // --- Phase A: compaction ----------------------------------------------
    #pragma unroll
    for (int k = 0; k < 4; k++) {
        if (u[k].x | u[k].y | u[k].z | u[k].w) {
            int bj = (tid + k * 512) * 4;
            if (u[k].x) { int p = atomicAdd(&cnt, 1); idxs[p] = bj;     }
            if (u[k].y) { int p = atomicAdd(&cnt, 1); idxs[p] = bj + 1; }
            if (u[k].z) { int p = atomicAdd(&cnt, 1); idxs[p] = bj + 2; }
            if (u[k].w) { int p = atomicAdd(&cnt, 1); idxs[p] = bj + 3; }
        }
    }
    __syncthreads();
    const int m = cnt;

    // --- Phase B: half-warp per element ------------------------------------
    const int half = lane >> 4;                       // 0 or 1
    const int hl   = lane & 15;
    const unsigned hmask = 0xFFFFu << (half * 16);
    const float4 x1v = *(const float4*)(x1s + hl * 4);
    float lsum = 0.f;

    for (int el = wid * 2 + half; el < m; el += 32) {
        const int j = idxs[el];
        const float bb = __ldg(B + rowoff + j);       // half-warp broadcast
        const float vv = __ldg(V + rowoff + j);
        const float4 xv = __ldg((const float4*)(g_X2 + (size_t)j * CC) + hl);
        float p = xv.x * x1v.x + xv.y * x1v.y + xv.z * x1v.z + xv.w * x1v.w;
        #pragma unroll
        for (int o = 8; o; o >>= 1) p += __shfl_xor_sync(hmask, p, o);
        if (hl == 0) {
            const float sg = 1.f / (1.f + expf(-(p + bb)));
            const float ev = expf(vv * sg);
            e_c[el] = ev;
            lsum += ev;
        }
    }

    // --- Row sum: warp reduce + one smem atomic per warp --------------------
    #pragma unroll
    for (int o = 16; o; o >>= 1) lsum += __shfl_down_sync(0xffffffffu, lsum, o);
    if (lane == 0 && lsum != 0.f) atomicAdd(&rowsum, lsum);
    __syncthreads();

    // --- Sparse scatter of scaled values over the zeros ---------------------
    const float inv = 1.f / rowsum;
    for (int el = tid; el < m; el += 512)
        __stcs(out + rowoff + idxs[el], e_c[el] * inv);
}

extern "C" void kernel_launch(void* const* d_in, const int* in_sizes, int n_in,
                              void* d_out, int out_size)
{
    (void)in_sizes; (void)n_in; (void)out_size;
    const float* Hp  = (const float*)d_in[0];
    const float* w1  = (const float*)d_in[1];
    const float* W2  = (const float*)d_in[2];
    const float* w3  = (const float*)d_in[3];
    const float* V   = (const float*)d_in[4];
    const float* B   = (const float*)d_in[5];
    const unsigned int* mask = (const unsigned int*)d_in[6];
    float* out = (float*)d_out;

    prep_kernel<<<NS / 2, 512>>>(Hp, w1, W2, w3);
    row_kernel<<<NS, 512>>>(V, B, mask, out);
}

// round 12
// speedup vs baseline: 1.5837x; 1.0979x over previous
#include <cuda_runtime.h>

#define NS 8192
#define NH 64
#define CC 64
#define TILES 4

// Scratch (allocation-free rule: __device__ globals)
__device__ float g_X1[NS * CC];
__device__ float g_X2[NS * CC];

// ---------------------------------------------------------------------------
// Kernel 1 (exact R8 version — best known at 38.2 us): 4 tiles per CTA,
// 256 threads, all 16 float4 loads front-batched, register-resident reductions.
// ---------------------------------------------------------------------------
__global__ void __launch_bounds__(256) prep_kernel(
    const float* __restrict__ Hp, const float* __restrict__ w1,
    const float* __restrict__ W2, const float* __restrict__ w3)
{
    __shared__ float t_sm[TILES][64];
    const int s0   = blockIdx.x * TILES;
    const int tid  = threadIdx.x;
    const int lane = tid & 31;

    ((float*)t_sm)[tid] = 0.f;   // 256 floats == TILES*64

    // Front-batched streaming loads (read-once: evict-first)
    const float4* base = (const float4*)(Hp + (size_t)s0 * (CC * NH));
    float4 v[TILES][4];
    #pragma unroll
    for (int p = 0; p < TILES; p++)
        #pragma unroll
        for (int k = 0; k < 4; k++)
            v[p][k] = __ldcs(base + p * 1024 + tid + 256 * k);

    const int h0 = (tid & 15) * 4;
    const int c0 = tid >> 4;
    const float w3v0 = __ldg(w3 + h0),     w3v1 = __ldg(w3 + h0 + 1);
    const float w3v2 = __ldg(w3 + h0 + 2), w3v3 = __ldg(w3 + h0 + 3);
    float w1c[4];
    #pragma unroll
    for (int k = 0; k < 4; k++) w1c[k] = __ldg(w1 + c0 + 16 * k);

    __syncthreads();   // t_sm init visible before atomics

    #pragma unroll
    for (int p = 0; p < TILES; p++) {
        float tq0 = 0.f, tq1 = 0.f, tq2 = 0.f, tq3 = 0.f;
        #pragma unroll
        for (int k = 0; k < 4; k++) {
            tq0 += v[p][k].x * w1c[k];  tq1 += v[p][k].y * w1c[k];
            tq2 += v[p][k].z * w1c[k];  tq3 += v[p][k].w * w1c[k];

            float d = v[p][k].x * w3v0 + v[p][k].y * w3v1
                    + v[p][k].z * w3v2 + v[p][k].w * w3v3;
            #pragma unroll
            for (int o = 8; o; o >>= 1) d += __shfl_xor_sync(0xffffffffu, d, o);
            if ((lane & 15) == 0)
                g_X2[(size_t)(s0 + p) * CC + c0 + 16 * k] = d;
        }
        tq0 += __shfl_xor_sync(0xffffffffu, tq0, 16);
        tq1 += __shfl_xor_sync(0xffffffffu, tq1, 16);
        tq2 += __shfl_xor_sync(0xffffffffu, tq2, 16);
        tq3 += __shfl_xor_sync(0xffffffffu, tq3, 16);
        if (lane < 16) {
            atomicAdd(&t_sm[p][h0],     tq0);
            atomicAdd(&t_sm[p][h0 + 1], tq1);
            atomicAdd(&t_sm[p][h0 + 2], tq2);
            atomicAdd(&t_sm[p][h0 + 3], tq3);
        }
    }
    __syncthreads();

    const int cp   = tid >> 2;
    const int part = tid & 3;
    const float4* w2v = (const float4*)(W2 + cp * NH + part * 16);
    float4 w[4];
    #pragma unroll
    for (int j = 0; j < 4; j++) w[j] = __ldg(&w2v[j]);

    #pragma unroll
    for (int p = 0; p < TILES; p++) {
        const float* tp = &t_sm[p][part * 16];
        float acc = 0.f;
        #pragma unroll
        for (int j = 0; j < 4; j++)
            acc += w[j].x * tp[4*j] + w[j].y * tp[4*j+1]
                 + w[j].z * tp[4*j+2] + w[j].w * tp[4*j+3];
        acc += __shfl_xor_sync(0xffffffffu, acc, 1);
        acc += __shfl_xor_sync(0xffffffffu, acc, 2);
        if (part == 0) g_X1[(size_t)(s0 + p) * CC + cp] = acc;
    }
}

// ---------------------------------------------------------------------------
// Kernel 2: one CTA (512 thr) per row s — R8 structure; compaction now uses
// warp-aggregated prefix-scan allocation (ONE smem atomic per warp instead of
// ~82 serialized single-address atomics per CTA).
// ---------------------------------------------------------------------------
#define MAXM 2048   // binomial(8192, 0.01): mean 82, std 9 — huge margin

__global__ void __launch_bounds__(512) row_kernel(
    const float* __restrict__ V, const float* __restrict__ B,
    const unsigned int* __restrict__ mask, float* __restrict__ out)
{
    __shared__ int   idxs[MAXM];    // 8 KB compacted column indices
    __shared__ float e_c[MAXM];     // 8 KB compacted e values
    __shared__ float x1s[64];
    __shared__ float rowsum;
    __shared__ int   cnt;

    const int s    = blockIdx.x;
    const int tid  = threadIdx.x;
    const int lane = tid & 31;
    const int wid  = tid >> 5;
    const size_t rowoff = (size_t)s * NS;

    if (tid == 0) { cnt = 0; rowsum = 1e-6f; }
    if (tid < 64) x1s[tid] = g_X1[(size_t)s * CC + tid];

    // Front-batch the mask loads (evict-first: read exactly once)
    const uint4* mv = (const uint4*)(mask + rowoff);
    uint4 u[4];
    #pragma unroll
    for (int k = 0; k < 4; k++) u[k] = __ldcs(mv + tid + k * 512);

    // Fire-and-forget streaming zero write of the output row
    float4* out4 = (float4*)(out + rowoff);
    const float4 z4 = make_float4(0.f, 0.f, 0.f, 0.f);
    #pragma unroll
    for (int k = 0; k < 4; k++) __stcs(out4 + tid + k * 512, z4);

    __syncthreads();   // cnt/rowsum/x1s visible

    // --- Phase A: warp-aggregated compaction --------------------------------
    int nh = 0;
    #pragma unroll
    for (int k = 0; k < 4; k++)
        nh += (u[k].x ? 1 : 0) + (u[k].y ? 1 : 0)
            + (u[k].z ? 1 : 0) + (u[k].w ? 1 : 0);

    // Warp inclusive scan of hit counts
    int incl = nh;
    #pragma unroll
    for (int o = 1; o < 32; o <<= 1) {
        int t = __shfl_up_sync(0xffffffffu, incl, o);
        if (lane >= o) incl += t;
    }
    int wbase = 0;
    if (lane == 31 && incl > 0) wbase = atomicAdd(&cnt, incl);
    wbase = __shfl_sync(0xffffffffu, wbase, 31);

    int pos = wbase + incl - nh;   // exclusive prefix within warp
    #pragma unroll
    for (int k = 0; k < 4; k++) {
        if (u[k].x | u[k].y | u[k].z | u[k].w) {
            const int bj = (tid + k * 512) * 4;
            if (u[k].x) idxs[pos++] = bj;
            if (u[k].y) idxs[pos++] = bj + 1;
            if (u[k].z) idxs[pos++] = bj + 2;
            if (u[k].w) idxs[pos++] = bj + 3;
        }
    }
    __syncthreads();
    const int m = cnt;

    // --- Phase B: half-warp per element ------------------------------------
    const int half = lane >> 4;                       // 0 or 1
    const int hl   = lane & 15;
    const unsigned hmask = 0xFFFFu << (half * 16);
    const float4 x1v = *(const float4*)(x1s + hl * 4);
    float lsum = 0.f;

    for (int el = wid * 2 + half; el < m; el += 32) {
        const int j = idxs[el];
        const float bb = __ldg(B + rowoff + j);       // half-warp broadcast
        const float vv = __ldg(V + rowoff + j);
        const float4 xv = __ldg((const float4*)(g_X2 + (size_t)j * CC) + hl);
        float p = xv.x * x1v.x + xv.y * x1v.y + xv.z * x1v.z + xv.w * x1v.w;
        #pragma unroll
        for (int o = 8; o; o >>= 1) p += __shfl_xor_sync(hmask, p, o);
        if (hl == 0) {
            const float sg = 1.f / (1.f + expf(-(p + bb)));
            const float ev = expf(vv * sg);
            e_c[el] = ev;
            lsum += ev;
        }
    }

    // --- Row sum: warp reduce + one smem atomic per warp --------------------
    #pragma unroll
    for (int o = 16; o; o >>= 1) lsum += __shfl_down_sync(0xffffffffu, lsum, o);
    if (lane == 0 && lsum != 0.f) atomicAdd(&rowsum, lsum);
    __syncthreads();

    // --- Sparse scatter of scaled values over the zeros ---------------------
    const float inv = 1.f / rowsum;
    for (int el = tid; el < m; el += 512)
        __stcs(out + rowoff + idxs[el], e_c[el] * inv);
}

extern "C" void kernel_launch(void* const* d_in, const int* in_sizes, int n_in,
                              void* d_out, int out_size)
{
    (void)in_sizes; (void)n_in; (void)out_size;
    const float* Hp  = (const float*)d_in[0];
    const float* w1  = (const float*)d_in[1];
    const float* W2  = (const float*)d_in[2];
    const float* w3  = (const float*)d_in[3];
    const float* V   = (const float*)d_in[4];
    const float* B   = (const float*)d_in[5];
    const unsigned int* mask = (const unsigned int*)d_in[6];
    float* out = (float*)d_out;

    prep_kernel<<<NS / TILES, 256>>>(Hp, w1, W2, w3);
    row_kernel<<<NS, 512>>>(V, B, mask, out);
}